// round 14
// baseline (speedup 1.0000x reference)
#include <cuda_runtime.h>
#include <cuda_fp16.h>
#include <math.h>
#include <cstdint>

#define PDIM    4354
#define PADK    4480            // K padded: 70 chunks x 64
#define PADP    4480
#define NCHUNK  70
#define NPBLK   69              // 69 x 64 = 4416 >= 4354
#define BATCH   32
#define SEQ     64

// Split scales (Ootomo): v = h + 2^-11 m', both operands fp16-normal.
#define S1F     2048.0f
#define S1I     (1.0f / 2048.0f)

// smem per buffer (fp16, rows padded to 72 elems = 144 B):
//   Ahi 64x144 (9216) | Ami 9216 | Thi 32x144 (4608) | Tmi 4608 = 27648 B
#define STRIDE_B   144
#define OFF_AHI    0
#define OFF_AMI    9216
#define OFF_THI    18432
#define OFF_TMI    23040
#define BUFSZ      27648
#define NBUF       4
#define TILE0      1024
#define SMEM_BYTES (TILE0 + NBUF * BUFSZ)   // 111616

// Static device scratch.
__device__ __align__(16) __half g_Ahi[(size_t)PADP * PADK];
__device__ __align__(16) __half g_Ami[(size_t)PADP * PADK];
__device__ __align__(16) float  g_theta[2][BATCH * PADK];
__device__ __align__(16) __half g_Thi[2][BATCH * PADK];
__device__ __align__(16) __half g_Tmi[2][BATCH * PADK];
__device__ float g_u[BATCH];
__device__ float g_xprev[BATCH];

// ---------------------------------------------------------------------------
// PTX helpers (all baseline sm_80+ — safe for the sm_103 (non-'a') ptxas pass)
// ---------------------------------------------------------------------------
__device__ __forceinline__ uint32_t smem_u32(const void* p) {
    uint32_t a;
    asm("{ .reg .u64 t; cvta.to.shared.u64 t, %1; cvt.u32.u64 %0, t; }"
        : "=r"(a) : "l"(p));
    return a;
}
#define CP16(dst, src) \
    asm volatile("cp.async.cg.shared.global [%0], [%1], 16;" :: "r"(dst), "l"(src) : "memory")
#define CP_COMMIT() asm volatile("cp.async.commit_group;" ::: "memory")
#define CP_WAIT3()  asm volatile("cp.async.wait_group 3;" ::: "memory")

#define LDSM4(r0, r1, r2, r3, addr) \
    asm volatile("ldmatrix.sync.aligned.m8n8.x4.shared.b16 {%0,%1,%2,%3}, [%4];" \
                 : "=r"(r0), "=r"(r1), "=r"(r2), "=r"(r3) : "r"(addr))

// In-mma accumulate (2^-11-scaled group: RZ bias enters * 2^-11 — negligible).
#define MMA16816(c, a0, a1, a2, a3, b0, b1) \
    asm volatile("mma.sync.aligned.m16n8k16.row.col.f32.f16.f16.f32 " \
                 "{%0,%1,%2,%3}, {%4,%5,%6,%7}, {%8,%9}, {%0,%1,%2,%3};" \
                 : "+f"((c)[0]), "+f"((c)[1]), "+f"((c)[2]), "+f"((c)[3]) \
                 : "r"(a0), "r"(a1), "r"(a2), "r"(a3), "r"(b0), "r"(b1))

// Zero-C version: running sum added OUTSIDE the tensor core (RN fp32, no bias).
#define MMA16816_ZC(d, a0, a1, a2, a3, b0, b1) \
    asm volatile("mma.sync.aligned.m16n8k16.row.col.f32.f16.f16.f32 " \
                 "{%0,%1,%2,%3}, {%4,%5,%6,%7}, {%8,%9}, {%10,%10,%10,%10};" \
                 : "=f"((d)[0]), "=f"((d)[1]), "=f"((d)[2]), "=f"((d)[3]) \
                 : "r"(a0), "r"(a1), "r"(a2), "r"(a3), "r"(b0), "r"(b1), "f"(0.0f))

#define ACC4(c, d) \
    (c)[0] += (d)[0]; (c)[1] += (d)[1]; (c)[2] += (d)[2]; (c)[3] += (d)[3];

// Scaled 2-split: v = h + S1I*m ; h, m in fp16 NORMAL range.
__device__ __forceinline__ void split2s(float v, __half& h, __half& m) {
    h = __float2half_rn(v);
    m = __float2half_rn((v - __half2float(h)) * S1F);
}

// ---------------------------------------------------------------------------
// Init 1: scaled 2-split of A -> fp16 hi/mid, zero-padded to PADP x PADK.
// ---------------------------------------------------------------------------
__global__ void init_A_kernel(const float* __restrict__ A) {
    size_t total = (size_t)PADP * PADK;
    for (size_t idx = blockIdx.x * (size_t)blockDim.x + threadIdx.x;
         idx < total; idx += (size_t)gridDim.x * blockDim.x) {
        int p = (int)(idx / PADK);
        int k = (int)(idx - (size_t)p * PADK);
        float a = (p < PDIM && k < PDIM) ? A[(size_t)p * PDIM + k] : 0.0f;
        __half h, m;
        split2s(a, h, m);
        g_Ahi[idx] = h;
        g_Ami[idx] = m;
    }
}

// ---------------------------------------------------------------------------
// Init 2: theta fp32 + scaled 2-splits (buf0 = theta_init, buf1 = 0).
// ---------------------------------------------------------------------------
__global__ void init_theta_kernel(const float* __restrict__ theta_init) {
    int total = 2 * BATCH * PADK;
    for (int idx = blockIdx.x * blockDim.x + threadIdx.x;
         idx < total; idx += gridDim.x * blockDim.x) {
        int buf = idx / (BATCH * PADK);
        int k = (idx - buf * (BATCH * PADK)) % PADK;
        float v = (buf == 0 && k < PDIM) ? theta_init[k] : 0.0f;
        __half h, m;
        split2s(v, h, m);
        ((float*)g_theta)[idx] = v;
        ((__half*)g_Thi)[idx]  = h;
        ((__half*)g_Tmi)[idx]  = m;
    }
    int i0 = blockIdx.x * blockDim.x + threadIdx.x;
    if (i0 < BATCH) g_xprev[i0] = 0.0f;
}

// ---------------------------------------------------------------------------
// Prep kernel: one block per batch; tiny 5-layer MLP + carry update.
// ---------------------------------------------------------------------------
__global__ __launch_bounds__(32) void prep_kernel(
    const float* __restrict__ xs,
    const float* __restrict__ noise,
    const int*   __restrict__ inf_start_p,
    float*       __restrict__ out,
    int t, int par)
{
    int b    = blockIdx.x;
    int lane = threadIdx.x;
    const float* __restrict__ th = g_theta[par] + b * PADK;

    float x = (float)t / (float)SEQ;
    float y = x * th[lane] + th[32 + lane];
    y = y / (1.0f + expf(-y));

    #pragma unroll
    for (int l = 0; l < 4; l++) {
        int base = 64 + l * 1056;
        const float4* wp = reinterpret_cast<const float4*>(th + base + lane * 32);
        float4 w[8];
        #pragma unroll
        for (int q = 0; q < 8; q++) w[q] = wp[q];
        float acc = th[base + 1024 + lane];
        #pragma unroll
        for (int q = 0; q < 8; q++) {
            float y0 = __shfl_sync(0xffffffffu, y, q * 4 + 0);
            float y1 = __shfl_sync(0xffffffffu, y, q * 4 + 1);
            float y2 = __shfl_sync(0xffffffffu, y, q * 4 + 2);
            float y3 = __shfl_sync(0xffffffffu, y, q * 4 + 3);
            acc = fmaf(w[q].x, y0, acc);
            acc = fmaf(w[q].y, y1, acc);
            acc = fmaf(w[q].z, y2, acc);
            acc = fmaf(w[q].w, y3, acc);
        }
        y = acc / (1.0f + expf(-acc));
    }

    float s0 = 0.0f, s1 = 0.0f;
    #pragma unroll
    for (int ii = 0; ii < 32; ii++) {
        float yi = __shfl_sync(0xffffffffu, y, ii);
        s0 = fmaf(yi, th[4288 + ii], s0);
        s1 = fmaf(yi, th[4320 + ii], s1);
    }

    if (lane == 0) {
        float mean = tanhf(s0 + th[4352]);
        float lv   = fminf(fmaxf(s1 + th[4353], -4.0f), 4.0f);
        float sd   = expf(0.5f * lv);
        out[b * SEQ + t] = mean;
        out[BATCH * SEQ + b * SEQ + t] = sd;
        float nz   = noise[t * BATCH + b];
        float xhat = nz * sd + mean;
        float xt   = (t < *inf_start_p) ? xs[b * SEQ + t] : xhat;
        g_u[b]     = xt - g_xprev[b];
        g_xprev[b] = xt;
    }
}

// ---------------------------------------------------------------------------
// GEMM step: theta_next = clip(theta @ A^T + u*B^T, -1, 1) via mma.sync fp16
// Scaled 2-split, 2 accumulator groups (acc0 = hh zero-C + RN adds; acc1 =
// hm + mh in-mma). 69 CTAs x 256 thr; CTA tile 64p x 32b; 4-stage pipeline.
// Warp w: P-group pg=w&3 (16 rows), K-half kh=w>>2 (32 of 64 chunk cols).
// ---------------------------------------------------------------------------
__device__ __forceinline__ void issue_chunk(int j, uint32_t sb, int tid, int p0, int par) {
    uint32_t buf = sb + TILE0 + (j & (NBUF - 1)) * BUFSZ;
    int kbase = j * 64;
    // A: 64 rows x 8 segs = 512 slots; 256 threads x 2.
    #pragma unroll
    for (int i = 0; i < 2; i++) {
        int idx = tid + 256 * i;
        int r = idx >> 3, s = idx & 7;
        uint32_t off = buf + r * STRIDE_B + s * 16;
        size_t ga = (size_t)(p0 + r) * PADK + kbase + s * 8;
        CP16(off + OFF_AHI, g_Ahi + ga);
        CP16(off + OFF_AMI, g_Ami + ga);
    }
    // T: 32 rows x 8 segs = 256 slots.
    {
        int r = tid >> 3, s = tid & 7;
        uint32_t off = buf + r * STRIDE_B + s * 16;
        size_t gt = (size_t)r * PADK + kbase + s * 8;
        CP16(off + OFF_THI, g_Thi[par] + gt);
        CP16(off + OFF_TMI, g_Tmi[par] + gt);
    }
}

__global__ __launch_bounds__(256) void gemm_kernel(const float* __restrict__ Bv, int par) {
    extern __shared__ char smem[];
    uint32_t sb = smem_u32(smem);
    int tid  = threadIdx.x;
    int wid  = tid >> 5;
    int lane = tid & 31;
    int pg   = wid & 3;          // P-group (16 rows)
    int kh   = wid >> 2;         // K-half (32 cols of each 64 chunk)
    int p0   = blockIdx.x * 64;

    float* u_s  = (float*)smem;          // [32]
    float* bv_s = (float*)smem + 32;     // [64]
    if (tid < 32) u_s[tid] = g_u[tid];
    if (tid >= 64 && tid < 128) {
        int i = tid - 64;
        int p = p0 + i;
        bv_s[i] = (p < PDIM) ? Bv[p] : 0.0f;
    }

    float acc0[4][4], acc1[4][4];
    #pragma unroll
    for (int nt = 0; nt < 4; nt++)
        #pragma unroll
        for (int j = 0; j < 4; j++) { acc0[nt][j] = 0.0f; acc1[nt][j] = 0.0f; }

    int aRow  = pg * 16 + (lane & 15);
    int aKoff = (lane >> 4) * 8;
    int krel  = kh * 32;

    // Prologue: fill 3 stages.
    issue_chunk(0, sb, tid, p0, par); CP_COMMIT();
    issue_chunk(1, sb, tid, p0, par); CP_COMMIT();
    issue_chunk(2, sb, tid, p0, par); CP_COMMIT();

    for (int ch = 0; ch < NCHUNK; ch++) {
        if (ch + 3 < NCHUNK) issue_chunk(ch + 3, sb, tid, p0, par);
        CP_COMMIT();            // empty group past the end — uniform group count
        CP_WAIT3();             // chunk ch's group complete
        __syncthreads();

        uint32_t buf = sb + TILE0 + (ch & (NBUF - 1)) * BUFSZ;

        #pragma unroll
        for (int kk = 0; kk < 2; kk++) {
            int k16 = krel + kk * 16;
            uint32_t aAddr = buf + aRow * STRIDE_B + (k16 + aKoff) * 2;
            uint32_t ah0, ah1, ah2, ah3, am0, am1, am2, am3;
            LDSM4(ah0, ah1, ah2, ah3, aAddr + OFF_AHI);
            LDSM4(am0, am1, am2, am3, aAddr + OFF_AMI);

            uint32_t tAddr = buf + lane * STRIDE_B + k16 * 2;
            uint32_t bh0[4], bh8[4], bm0[4], bm8[4];
            LDSM4(bh0[0], bh0[1], bh0[2], bh0[3], tAddr + OFF_THI);
            LDSM4(bh8[0], bh8[1], bh8[2], bh8[3], tAddr + OFF_THI + 16);
            LDSM4(bm0[0], bm0[1], bm0[2], bm0[3], tAddr + OFF_TMI);
            LDSM4(bm8[0], bm8[1], bm8[2], bm8[3], tAddr + OFF_TMI + 16);

            #pragma unroll
            for (int nt = 0; nt < 4; nt++) {
                float d[4];
                MMA16816_ZC(d, ah0, ah1, ah2, ah3, bh0[nt], bh8[nt]);       // hh
                ACC4(acc0[nt], d);
                MMA16816(acc1[nt], ah0, ah1, ah2, ah3, bm0[nt], bm8[nt]);   // hm
                MMA16816(acc1[nt], am0, am1, am2, am3, bh0[nt], bh8[nt]);   // mh
            }
        }
        __syncthreads();
    }

    // Combine scale groups, then split-K x2 reduction.
    float loc[4][4];
    #pragma unroll
    for (int nt = 0; nt < 4; nt++)
        #pragma unroll
        for (int j = 0; j < 4; j++)
            loc[nt][j] = fmaf(S1I, acc1[nt][j], acc0[nt][j]);

    float* red = (float*)(smem + TILE0);   // [64 r][32 c] = 8 KB (reuses bufs)
    int r   = lane >> 2;
    int cpr = (lane & 3) * 2;

    if (kh == 1) {
        #pragma unroll
        for (int nt = 0; nt < 4; nt++) {
            int c = nt * 8 + cpr;
            red[(pg * 16 + r) * 32 + c]         = loc[nt][0];
            red[(pg * 16 + r) * 32 + c + 1]     = loc[nt][1];
            red[(pg * 16 + r + 8) * 32 + c]     = loc[nt][2];
            red[(pg * 16 + r + 8) * 32 + c + 1] = loc[nt][3];
        }
    }
    __syncthreads();

    if (kh == 0) {
        float*  oF = g_theta[par ^ 1];
        __half* oH = g_Thi[par ^ 1];
        __half* oM = g_Tmi[par ^ 1];
        #pragma unroll
        for (int nt = 0; nt < 4; nt++) {
            int c = nt * 8 + cpr;
            #pragma unroll
            for (int j = 0; j < 4; j++) {
                int rr = (j >> 1) ? r + 8 : r;
                int cc = c + (j & 1);
                int lr = pg * 16 + rr;
                int p  = p0 + lr;
                if (p < PDIM) {
                    float v = loc[nt][j] + red[lr * 32 + cc];
                    v = fmaf(u_s[cc], bv_s[lr], v);
                    v = fminf(fmaxf(v, -1.0f), 1.0f);
                    __half h, m;
                    split2s(v, h, m);
                    size_t o = (size_t)cc * PADK + p;
                    oF[o] = v;
                    oH[o] = h;
                    oM[o] = m;
                }
            }
        }
    }
}

// ---------------------------------------------------------------------------
// kernel_launch
// ---------------------------------------------------------------------------
extern "C" void kernel_launch(void* const* d_in, const int* in_sizes, int n_in,
                              void* d_out, int out_size) {
    const float* xs         = (const float*)d_in[0];
    const float* noise      = (const float*)d_in[1];
    const float* theta_init = (const float*)d_in[2];
    const float* A          = (const float*)d_in[3];
    const float* Bv         = (const float*)d_in[4];
    const int*   inf_start  = (const int*)d_in[5];
    float*       out        = (float*)d_out;

    cudaFuncSetAttribute(gemm_kernel,
                         cudaFuncAttributeMaxDynamicSharedMemorySize, SMEM_BYTES);

    init_A_kernel<<<4096, 256>>>(A);
    init_theta_kernel<<<1120, 256>>>(theta_init);

    for (int t = 0; t < SEQ; t++) {
        int par = t & 1;
        prep_kernel<<<BATCH, 32>>>(xs, noise, inf_start, out, t, par);
        gemm_kernel<<<NPBLK, 256, SMEM_BYTES>>>(Bv, par);
    }
}

// round 15
// speedup vs baseline: 2.1812x; 2.1812x over previous
#include <cuda_runtime.h>
#include <cuda_fp16.h>
#include <math.h>
#include <cstdint>

#define PDIM    4354
#define PADK    4480            // K padded: 35 chunks x 128
#define PADP    4480
#define CHUNK   128
#define NCHUNK  35
#define NPBLK   137             // 137 x 32 = 4384 >= 4354
#define BATCH   32
#define SEQ     64
#define NTHR    512

// Split scales (Ootomo): v = h + 2^-11 m', both operands fp16-normal.
#define S1F     2048.0f
#define S1I     (1.0f / 2048.0f)

// smem per buffer (fp16, rows of 128 elems padded to 272 B = 17 segs):
//   Ahi 32x272 (8704) | Ami | Thi | Tmi  = 34816 B; 4-stage pipeline.
#define STRIDE_B   272
#define OFF_AHI    0
#define OFF_AMI    8704
#define OFF_THI    17408
#define OFF_TMI    26112
#define BUFSZ      34816
#define NBUF       4
#define TILE0      1024
#define SMEM_BYTES (TILE0 + NBUF * BUFSZ)   // 140288

// Static device scratch.
__device__ __align__(16) __half g_Ahi[(size_t)PADP * PADK];
__device__ __align__(16) __half g_Ami[(size_t)PADP * PADK];
__device__ __align__(16) float  g_theta[2][BATCH * PADK];
__device__ __align__(16) __half g_Thi[2][BATCH * PADK];
__device__ __align__(16) __half g_Tmi[2][BATCH * PADK];
__device__ float g_u[BATCH];
__device__ float g_xprev[BATCH];

// ---------------------------------------------------------------------------
// PTX helpers (all baseline sm_80+ — safe for the sm_103 (non-'a') ptxas pass)
// ---------------------------------------------------------------------------
__device__ __forceinline__ uint32_t smem_u32(const void* p) {
    uint32_t a;
    asm("{ .reg .u64 t; cvta.to.shared.u64 t, %1; cvt.u32.u64 %0, t; }"
        : "=r"(a) : "l"(p));
    return a;
}
#define CP16(dst, src) \
    asm volatile("cp.async.cg.shared.global [%0], [%1], 16;" :: "r"(dst), "l"(src) : "memory")
#define CP_COMMIT() asm volatile("cp.async.commit_group;" ::: "memory")
#define CP_WAIT3()  asm volatile("cp.async.wait_group 3;" ::: "memory")

#define LDSM4(r0, r1, r2, r3, addr) \
    asm volatile("ldmatrix.sync.aligned.m8n8.x4.shared.b16 {%0,%1,%2,%3}, [%4];" \
                 : "=r"(r0), "=r"(r1), "=r"(r2), "=r"(r3) : "r"(addr))

// In-mma accumulate (2^-11-scaled group: RZ bias enters * 2^-11 — negligible).
#define MMA16816(c, a0, a1, a2, a3, b0, b1) \
    asm volatile("mma.sync.aligned.m16n8k16.row.col.f32.f16.f16.f32 " \
                 "{%0,%1,%2,%3}, {%4,%5,%6,%7}, {%8,%9}, {%0,%1,%2,%3};" \
                 : "+f"((c)[0]), "+f"((c)[1]), "+f"((c)[2]), "+f"((c)[3]) \
                 : "r"(a0), "r"(a1), "r"(a2), "r"(a3), "r"(b0), "r"(b1))

// Zero-C version: running sum added OUTSIDE the tensor core (RN fp32, no bias).
#define MMA16816_ZC(d, a0, a1, a2, a3, b0, b1) \
    asm volatile("mma.sync.aligned.m16n8k16.row.col.f32.f16.f16.f32 " \
                 "{%0,%1,%2,%3}, {%4,%5,%6,%7}, {%8,%9}, {%10,%10,%10,%10};" \
                 : "=f"((d)[0]), "=f"((d)[1]), "=f"((d)[2]), "=f"((d)[3]) \
                 : "r"(a0), "r"(a1), "r"(a2), "r"(a3), "r"(b0), "r"(b1), "f"(0.0f))

#define ACC4(c, d) \
    (c)[0] += (d)[0]; (c)[1] += (d)[1]; (c)[2] += (d)[2]; (c)[3] += (d)[3];

// Scaled 2-split: v = h + S1I*m ; h, m in fp16 NORMAL range.
__device__ __forceinline__ void split2s(float v, __half& h, __half& m) {
    h = __float2half_rn(v);
    m = __float2half_rn((v - __half2float(h)) * S1F);
}

// ---------------------------------------------------------------------------
// Init 1: scaled 2-split of A -> fp16 hi/mid, zero-padded to PADP x PADK.
// ---------------------------------------------------------------------------
__global__ void init_A_kernel(const float* __restrict__ A) {
    size_t total = (size_t)PADP * PADK;
    for (size_t idx = blockIdx.x * (size_t)blockDim.x + threadIdx.x;
         idx < total; idx += (size_t)gridDim.x * blockDim.x) {
        int p = (int)(idx / PADK);
        int k = (int)(idx - (size_t)p * PADK);
        float a = (p < PDIM && k < PDIM) ? A[(size_t)p * PDIM + k] : 0.0f;
        __half h, m;
        split2s(a, h, m);
        g_Ahi[idx] = h;
        g_Ami[idx] = m;
    }
}

// ---------------------------------------------------------------------------
// Init 2: theta fp32 + scaled 2-splits (buf0 = theta_init, buf1 = 0).
// ---------------------------------------------------------------------------
__global__ void init_theta_kernel(const float* __restrict__ theta_init) {
    int total = 2 * BATCH * PADK;
    for (int idx = blockIdx.x * blockDim.x + threadIdx.x;
         idx < total; idx += gridDim.x * blockDim.x) {
        int buf = idx / (BATCH * PADK);
        int k = (idx - buf * (BATCH * PADK)) % PADK;
        float v = (buf == 0 && k < PDIM) ? theta_init[k] : 0.0f;
        __half h, m;
        split2s(v, h, m);
        ((float*)g_theta)[idx] = v;
        ((__half*)g_Thi)[idx]  = h;
        ((__half*)g_Tmi)[idx]  = m;
    }
    int i0 = blockIdx.x * blockDim.x + threadIdx.x;
    if (i0 < BATCH) g_xprev[i0] = 0.0f;
}

// ---------------------------------------------------------------------------
// Prep kernel: one block per batch; tiny 5-layer MLP + carry update.
// ---------------------------------------------------------------------------
__global__ __launch_bounds__(32) void prep_kernel(
    const float* __restrict__ xs,
    const float* __restrict__ noise,
    const int*   __restrict__ inf_start_p,
    float*       __restrict__ out,
    int t, int par)
{
    int b    = blockIdx.x;
    int lane = threadIdx.x;
    const float* __restrict__ th = g_theta[par] + b * PADK;

    float x = (float)t / (float)SEQ;
    float y = x * th[lane] + th[32 + lane];
    y = y / (1.0f + expf(-y));

    #pragma unroll
    for (int l = 0; l < 4; l++) {
        int base = 64 + l * 1056;
        const float4* wp = reinterpret_cast<const float4*>(th + base + lane * 32);
        float4 w[8];
        #pragma unroll
        for (int q = 0; q < 8; q++) w[q] = wp[q];
        float acc = th[base + 1024 + lane];
        #pragma unroll
        for (int q = 0; q < 8; q++) {
            float y0 = __shfl_sync(0xffffffffu, y, q * 4 + 0);
            float y1 = __shfl_sync(0xffffffffu, y, q * 4 + 1);
            float y2 = __shfl_sync(0xffffffffu, y, q * 4 + 2);
            float y3 = __shfl_sync(0xffffffffu, y, q * 4 + 3);
            acc = fmaf(w[q].x, y0, acc);
            acc = fmaf(w[q].y, y1, acc);
            acc = fmaf(w[q].z, y2, acc);
            acc = fmaf(w[q].w, y3, acc);
        }
        y = acc / (1.0f + expf(-acc));
    }

    float s0 = 0.0f, s1 = 0.0f;
    #pragma unroll
    for (int ii = 0; ii < 32; ii++) {
        float yi = __shfl_sync(0xffffffffu, y, ii);
        s0 = fmaf(yi, th[4288 + ii], s0);
        s1 = fmaf(yi, th[4320 + ii], s1);
    }

    if (lane == 0) {
        float mean = tanhf(s0 + th[4352]);
        float lv   = fminf(fmaxf(s1 + th[4353], -4.0f), 4.0f);
        float sd   = expf(0.5f * lv);
        out[b * SEQ + t] = mean;
        out[BATCH * SEQ + b * SEQ + t] = sd;
        float nz   = noise[t * BATCH + b];
        float xhat = nz * sd + mean;
        float xt   = (t < *inf_start_p) ? xs[b * SEQ + t] : xhat;
        g_u[b]     = xt - g_xprev[b];
        g_xprev[b] = xt;
    }
}

// ---------------------------------------------------------------------------
// GEMM step: theta_next = clip(theta @ A^T + u*B^T, -1, 1) via mma.sync fp16
// Scaled 2-split, acc0 = hh (zero-C + RN adds), acc1 = hm + mh (in-mma).
// 137 CTAs x 512 thr; CTA tile 32p x 32b; K in 35 chunks of 128.
// Warp w: P-group pg=w&1 (16 rows), K-slice kh=w>>1 (16 of 128 chunk cols).
// Split-K x8, smem reduction. 4-stage cp.async pipeline.
// ---------------------------------------------------------------------------
__device__ __forceinline__ void issue_chunk(int j, uint32_t sb, int tid, int p0, int par) {
    uint32_t buf = sb + TILE0 + (j & (NBUF - 1)) * BUFSZ;
    int kbase = j * CHUNK;
    // 32 rows x 16 segs = 512 slots, one per thread, per array.
    int r = tid >> 4, s = tid & 15;
    uint32_t off = buf + r * STRIDE_B + s * 16;
    size_t ga = (size_t)(p0 + r) * PADK + kbase + s * 8;
    CP16(off + OFF_AHI, g_Ahi + ga);
    CP16(off + OFF_AMI, g_Ami + ga);
    size_t gt = (size_t)r * PADK + kbase + s * 8;
    CP16(off + OFF_THI, g_Thi[par] + gt);
    CP16(off + OFF_TMI, g_Tmi[par] + gt);
}

__global__ __launch_bounds__(NTHR) void gemm_kernel(const float* __restrict__ Bv, int par) {
    extern __shared__ char smem[];
    uint32_t sb = smem_u32(smem);
    int tid  = threadIdx.x;
    int wid  = tid >> 5;
    int lane = tid & 31;
    int pg   = wid & 1;          // P-group (16 rows)
    int kh   = wid >> 1;         // K-slice (16 cols of each 128 chunk), 0..7
    int p0   = blockIdx.x * 32;

    float* u_s  = (float*)smem;          // [32]
    float* bv_s = (float*)smem + 32;     // [32]
    if (tid < 32) u_s[tid] = g_u[tid];
    if (tid >= 64 && tid < 96) {
        int i = tid - 64;
        int p = p0 + i;
        bv_s[i] = (p < PDIM) ? Bv[p] : 0.0f;
    }

    float acc0[4][4], acc1[4][4];
    #pragma unroll
    for (int nt = 0; nt < 4; nt++)
        #pragma unroll
        for (int j = 0; j < 4; j++) { acc0[nt][j] = 0.0f; acc1[nt][j] = 0.0f; }

    int aRow  = pg * 16 + (lane & 15);
    int aKoff = (lane >> 4) * 8;
    int krel  = kh * 16;

    // Prologue: fill 3 stages.
    issue_chunk(0, sb, tid, p0, par); CP_COMMIT();
    issue_chunk(1, sb, tid, p0, par); CP_COMMIT();
    issue_chunk(2, sb, tid, p0, par); CP_COMMIT();

    for (int ch = 0; ch < NCHUNK; ch++) {
        if (ch + 3 < NCHUNK) issue_chunk(ch + 3, sb, tid, p0, par);
        CP_COMMIT();            // empty group past the end — uniform group count
        CP_WAIT3();             // chunk ch's group complete
        __syncthreads();

        uint32_t buf = sb + TILE0 + (ch & (NBUF - 1)) * BUFSZ;

        uint32_t aAddr = buf + aRow * STRIDE_B + (krel + aKoff) * 2;
        uint32_t ah0, ah1, ah2, ah3, am0, am1, am2, am3;
        LDSM4(ah0, ah1, ah2, ah3, aAddr + OFF_AHI);
        LDSM4(am0, am1, am2, am3, aAddr + OFF_AMI);

        uint32_t tAddr = buf + lane * STRIDE_B + krel * 2;
        uint32_t bh0[4], bh8[4], bm0[4], bm8[4];
        LDSM4(bh0[0], bh0[1], bh0[2], bh0[3], tAddr + OFF_THI);
        LDSM4(bh8[0], bh8[1], bh8[2], bh8[3], tAddr + OFF_THI + 16);
        LDSM4(bm0[0], bm0[1], bm0[2], bm0[3], tAddr + OFF_TMI);
        LDSM4(bm8[0], bm8[1], bm8[2], bm8[3], tAddr + OFF_TMI + 16);

        #pragma unroll
        for (int nt = 0; nt < 4; nt++) {
            float d[4];
            MMA16816_ZC(d, ah0, ah1, ah2, ah3, bh0[nt], bh8[nt]);       // hh
            ACC4(acc0[nt], d);
            MMA16816(acc1[nt], ah0, ah1, ah2, ah3, bm0[nt], bm8[nt]);   // hm
            MMA16816(acc1[nt], am0, am1, am2, am3, bh0[nt], bh8[nt]);   // mh
        }
        __syncthreads();
    }

    // Combine scale groups, then split-K x8 reduction.
    float loc[4][4];
    #pragma unroll
    for (int nt = 0; nt < 4; nt++)
        #pragma unroll
        for (int j = 0; j < 4; j++)
            loc[nt][j] = fmaf(S1I, acc1[nt][j], acc0[nt][j]);

    float* red = (float*)(smem + TILE0);   // [7][32 r][32 c] = 28 KB (reuses bufs)
    int r   = lane >> 2;
    int cpr = (lane & 3) * 2;

    if (kh > 0) {
        float* rd = red + (kh - 1) * 1024;
        #pragma unroll
        for (int nt = 0; nt < 4; nt++) {
            int c = nt * 8 + cpr;
            rd[(pg * 16 + r) * 32 + c]         = loc[nt][0];
            rd[(pg * 16 + r) * 32 + c + 1]     = loc[nt][1];
            rd[(pg * 16 + r + 8) * 32 + c]     = loc[nt][2];
            rd[(pg * 16 + r + 8) * 32 + c + 1] = loc[nt][3];
        }
    }
    __syncthreads();

    if (kh == 0) {
        float*  oF = g_theta[par ^ 1];
        __half* oH = g_Thi[par ^ 1];
        __half* oM = g_Tmi[par ^ 1];
        #pragma unroll
        for (int nt = 0; nt < 4; nt++) {
            int c = nt * 8 + cpr;
            #pragma unroll
            for (int j = 0; j < 4; j++) {
                int rr = (j >> 1) ? r + 8 : r;
                int cc = c + (j & 1);
                int lr = pg * 16 + rr;
                int p  = p0 + lr;
                if (p < PDIM) {
                    float v = loc[nt][j];
                    #pragma unroll
                    for (int q = 0; q < 7; q++)
                        v += red[q * 1024 + lr * 32 + cc];
                    v = fmaf(u_s[cc], bv_s[lr], v);
                    v = fminf(fmaxf(v, -1.0f), 1.0f);
                    __half h, m;
                    split2s(v, h, m);
                    size_t o = (size_t)cc * PADK + p;
                    oF[o] = v;
                    oH[o] = h;
                    oM[o] = m;
                }
            }
        }
    }
}

// ---------------------------------------------------------------------------
// kernel_launch
// ---------------------------------------------------------------------------
extern "C" void kernel_launch(void* const* d_in, const int* in_sizes, int n_in,
                              void* d_out, int out_size) {
    const float* xs         = (const float*)d_in[0];
    const float* noise      = (const float*)d_in[1];
    const float* theta_init = (const float*)d_in[2];
    const float* A          = (const float*)d_in[3];
    const float* Bv         = (const float*)d_in[4];
    const int*   inf_start  = (const int*)d_in[5];
    float*       out        = (float*)d_out;

    cudaFuncSetAttribute(gemm_kernel,
                         cudaFuncAttributeMaxDynamicSharedMemorySize, SMEM_BYTES);

    init_A_kernel<<<4096, 256>>>(A);
    init_theta_kernel<<<1120, 256>>>(theta_init);

    for (int t = 0; t < SEQ; t++) {
        int par = t & 1;
        prep_kernel<<<BATCH, 32>>>(xs, noise, inf_start, out, t, par);
        gemm_kernel<<<NPBLK, NTHR, SMEM_BYTES>>>(Bv, par);
    }
}